// round 5
// baseline (speedup 1.0000x reference)
#include <cuda_runtime.h>

// ---------------- problem constants ----------------
#define B_SZ   32     // batch
#define NROWS  48     // Lorig
#define NCOLS  24     // R (cols)
#define CIN    32     // input feature size
#define HID    256    // hidden
#define RB     768    // NCOLS * B_SZ
#define LSTEPS 71     // R + Lorig - 1
#define KTOT   544    // 2*HID + CIN

// ---------------- tiling ----------------
#define BM 48          // rows per block tile
#define BJ 32          // hidden-j per block tile (x6 gates = 192 W rows)
#define KC 32          // K chunk
#define NCHUNK 17      // 544 / 32
#define AS_STRIDE 50   // BM padded (even, keeps 8B alignment for LDS.64 pairs)
#define WS_STRIDE 193  // 192 padded (odd -> conflict-free STS)

// out layout: [output_all (768,71,512)] [hidden_col (32,48,256)] [hidden_row (32,24,256)]
#define OUTALL_N  (RB * LSTEPS * 2 * HID)   // 27,918,336
#define HC_N      (B_SZ * NROWS * HID)      // 393,216
#define HR_N      (B_SZ * NCOLS * HID)      // 196,608

// ping-pong recurrent state (device scratch; no allocations allowed)
__device__ float g_hrow[2][RB * HID];
__device__ float g_hcol[2][RB * HID];

__global__ void init_kernel() {
    int idx = blockIdx.x * blockDim.x + threadIdx.x;
    if (idx < RB * HID) {
        g_hrow[0][idx] = 0.0f;
        g_hcol[0][idx] = 0.0f;
    }
}

__device__ __forceinline__ float sigmoidf_(float x) {
    return 1.0f / (1.0f + expf(-x));
}

// One recurrence step: fused GEMM (gate = [h_row|h_col|x_s] @ W^T + mask*Bp) + PSGMU update.
// Grid: (8 j-tiles, 16 m-tiles), 256 threads. Thread tile: 6 rows x 1 j x 6 gates,
// rows packed in pairs for fma.rn.f32x2 (Blackwell packed fp32 -> 2x FFMA rate).
__global__ __launch_bounds__(256, 1)
void step_kernel(const float* __restrict__ input,
                 const float* __restrict__ W,
                 const float* __restrict__ Bp,
                 float* __restrict__ out,
                 int s)
{
    __shared__ float As[KC][AS_STRIDE];   // A chunk, layout [k][row]
    __shared__ float Ws[KC][WS_STRIDE];   // W chunk, layout [k][gate*32 + j]

    const int tid = threadIdx.x;
    const int tx  = tid & 31;    // j within tile
    const int ty  = tid >> 5;    // row group (0..7), 6 rows each
    const int j0  = blockIdx.x * BJ;
    const int m0  = blockIdx.y * BM;

    const float* __restrict__ hrow_in  = g_hrow[s & 1];
    const float* __restrict__ hcol_in  = g_hcol[s & 1];
    float* __restrict__       hrow_out = g_hrow[(s + 1) & 1];
    float* __restrict__       hcol_out = g_hcol[(s + 1) & 1];

    unsigned long long acc[6][3];   // [gate][row-pair], packed f32x2
#pragma unroll
    for (int g = 0; g < 6; ++g)
#pragma unroll
        for (int p = 0; p < 3; ++p) acc[g][p] = 0ULL;

    const int arow = ty * 6;

    for (int c = 0; c < NCHUNK; ++c) {
        const int k0 = c * KC;

        // ---- stage A chunk: A[rb][k] = {h_row | rolled h_col | x_s}, stored transposed ----
        for (int u = tid; u < (BM * KC / 4); u += 256) {   // 384 float4
            int m  = u >> 3;
            int k4 = u & 7;
            int k  = k0 + (k4 << 2);
            int rb = m0 + m;
            float4 v;
            if (k < 256) {
                v = *reinterpret_cast<const float4*>(&hrow_in[rb * HID + k]);
            } else if (k < 512) {
                int src = rb - B_SZ; if (src < 0) src += RB;
                v = *reinterpret_cast<const float4*>(&hcol_in[src * HID + (k - 256)]);
            } else {
                int r = rb >> 5;
                int b = rb & 31;
                int l = s - r;
                if (l >= 0 && l < NROWS) {
                    int c0 = k - 512;
                    v = *reinterpret_cast<const float4*>(
                        &input[(((b * NROWS) + l) * NCOLS + r) * CIN + c0]);
                } else {
                    v = make_float4(0.f, 0.f, 0.f, 0.f);
                }
            }
            int kl = k4 << 2;
            As[kl + 0][m] = v.x; As[kl + 1][m] = v.y;
            As[kl + 2][m] = v.z; As[kl + 3][m] = v.w;
        }

        // ---- stage W chunk: rows {g*256 + j0 + jl : g=0..5, jl=0..31} ----
        for (int u = tid; u < (6 * BJ * KC / 4); u += 256) {  // 1536 float4
            int wrow = u >> 3;            // 0..191
            int k4   = u & 7;
            int k    = k0 + (k4 << 2);
            int g    = wrow >> 5;
            int jl   = wrow & 31;
            float4 v = *reinterpret_cast<const float4*>(
                &W[(g * HID + j0 + jl) * KTOT + k]);
            int kl = k4 << 2;
            Ws[kl + 0][wrow] = v.x; Ws[kl + 1][wrow] = v.y;
            Ws[kl + 2][wrow] = v.z; Ws[kl + 3][wrow] = v.w;
        }

        __syncthreads();

        // ---- compute: 18 packed-f32x2 FMAs per k per thread ----
#pragma unroll 8
        for (int kl = 0; kl < KC; ++kl) {
            unsigned long long a0 = *reinterpret_cast<const unsigned long long*>(&As[kl][arow + 0]);
            unsigned long long a1 = *reinterpret_cast<const unsigned long long*>(&As[kl][arow + 2]);
            unsigned long long a2 = *reinterpret_cast<const unsigned long long*>(&As[kl][arow + 4]);
#pragma unroll
            for (int g = 0; g < 6; ++g) {
                unsigned wu = __float_as_uint(Ws[kl][(g << 5) + tx]);
                unsigned long long wp;
                asm("mov.b64 %0, {%1, %1};" : "=l"(wp) : "r"(wu));
                asm("fma.rn.f32x2 %0, %1, %2, %0;" : "+l"(acc[g][0]) : "l"(a0), "l"(wp));
                asm("fma.rn.f32x2 %0, %1, %2, %0;" : "+l"(acc[g][1]) : "l"(a1), "l"(wp));
                asm("fma.rn.f32x2 %0, %1, %2, %0;" : "+l"(acc[g][2]) : "l"(a2), "l"(wp));
            }
        }
        __syncthreads();
    }

    // ---- fused PSGMU update + output write ----
    const int j = j0 + tx;
    float bp[6];
#pragma unroll
    for (int g = 0; g < 6; ++g) bp[g] = Bp[g * HID + j];
    const bool smask = (s < NCOLS);

#pragma unroll
    for (int p = 0; p < 3; ++p) {
#pragma unroll
        for (int h = 0; h < 2; ++h) {
            int m  = ty * 6 + p * 2 + h;
            int rb = m0 + m;
            int r  = rb >> 5;

            float gate[6];
#pragma unroll
            for (int g = 0; g < 6; ++g) {
                unsigned long long v = acc[g][p];
                unsigned bits = h ? (unsigned)(v >> 32) : (unsigned)(v & 0xffffffffULL);
                gate[g] = __uint_as_float(bits);
            }
            if (smask && (r <= s)) {
#pragma unroll
                for (int g = 0; g < 6; ++g) gate[g] += bp[g];
            }

            float u_row = sigmoidf_(gate[0]);
            float o_row = sigmoidf_(gate[1]);
            float u_col = sigmoidf_(gate[2]);
            float o_col = sigmoidf_(gate[3]);
            float i_row = tanhf(gate[4]);
            float i_col = tanhf(gate[5]);

            float hro = hrow_in[rb * HID + j];
            int src = rb - B_SZ; if (src < 0) src += RB;
            float hco = hcol_in[src * HID + j];

            float hr = tanhf((1.0f - u_row) * hro + u_row * i_row) * o_row;
            float hc = tanhf((1.0f - u_col) * hco + u_col * i_col) * o_col;

            hrow_out[rb * HID + j] = hr;
            hcol_out[rb * HID + j] = hc;

            float* orow = out + ((size_t)rb * LSTEPS + s) * (2 * HID);
            orow[j]       = hr;
            orow[HID + j] = hc;
        }
    }
}

// Gather hidden_col_all / hidden_row_all from output_all (disjoint regions of d_out).
__global__ void gather_kernel(float* __restrict__ out) {
    int idx = blockIdx.x * blockDim.x + threadIdx.x;
    if (idx < HC_N) {
        int b = idx / (NROWS * HID);
        int t = (idx / HID) % NROWS;
        int j = idx % HID;
        int rb = (NCOLS - 1) * B_SZ + b;      // r = 23
        int ss = (NCOLS - 1) + t;             // s = 23..70
        out[OUTALL_N + idx] = out[((size_t)rb * LSTEPS + ss) * (2 * HID) + HID + j];
    } else if (idx < HC_N + HR_N) {
        int k = idx - HC_N;
        int b = k / (NCOLS * HID);
        int i = (k / HID) % NCOLS;
        int j = k % HID;
        int rb = i * B_SZ + b;
        int ss = (NROWS - 1) + i;             // s = 47..70
        out[OUTALL_N + HC_N + k] = out[((size_t)rb * LSTEPS + ss) * (2 * HID) + j];
    }
}

extern "C" void kernel_launch(void* const* d_in, const int* in_sizes, int n_in,
                              void* d_out, int out_size) {
    (void)in_sizes; (void)n_in; (void)out_size;
    const float* input = (const float*)d_in[0];   // (32,48,24,32)
    const float* W     = (const float*)d_in[1];   // (1536,544)
    const float* Bp    = (const float*)d_in[2];   // (1536,)
    float* out = (float*)d_out;

    init_kernel<<<(RB * HID + 255) / 256, 256>>>();

    dim3 grid(HID / BJ, RB / BM);   // (8, 16) = 128 blocks
    for (int s = 0; s < LSTEPS; ++s) {
        step_kernel<<<grid, 256>>>(input, W, Bp, out, s);
    }

    gather_kernel<<<(HC_N + HR_N + 255) / 256, 256>>>(out);
}

// round 6
// speedup vs baseline: 1.5342x; 1.5342x over previous
#include <cuda_runtime.h>

// ---------------- problem constants ----------------
#define B_SZ   32
#define NROWS  48
#define NCOLS  24
#define CIN    32
#define HID    256
#define RB     768      // NCOLS * B_SZ
#define LSTEPS 71
#define KTOT   544      // 2*HID + CIN

// ---------------- tiling ----------------
#define BM     48       // rows per block
#define KC     32       // k per chunk
#define KP     16       // k-pairs per chunk
#define NCHUNK 17       // 544/32
#define WS_STRIDE 193   // 8-byte elements per klp row (192 cols + 1 pad)
#define WS_BUF (KP*WS_STRIDE)          // ull per W buffer
#define AS_FLOATS (BM*KTOT)            // 26112 floats
#define SMEM_BYTES (AS_FLOATS*4 + 2*WS_BUF*8)   // 104448 + 49408 = 153856

// out layout: [output_all (768,71,512)] [hidden_col (32,48,256)] [hidden_row (32,24,256)]
#define OUTALL_N  (RB * LSTEPS * 2 * HID)
#define HC_N      (B_SZ * NROWS * HID)
#define HR_N      (B_SZ * NCOLS * HID)

__device__ float g_hrow[2][RB * HID];
__device__ float g_hcol[2][RB * HID];

__global__ void init_kernel() {
    int idx = blockIdx.x * blockDim.x + threadIdx.x;
    if (idx < RB * HID) {
        g_hrow[0][idx] = 0.0f;
        g_hcol[0][idx] = 0.0f;
    }
}

__device__ __forceinline__ float sigmoidf_(float x) {
    return 1.0f / (1.0f + expf(-x));
}

__device__ __forceinline__ void cp16(void* dst, const void* src) {
    unsigned d = (unsigned)__cvta_generic_to_shared(dst);
    asm volatile("cp.async.ca.shared.global [%0], [%1], 16;" :: "r"(d), "l"(src));
}
__device__ __forceinline__ void cp16z(void* dst, const void* src) {
    unsigned d = (unsigned)__cvta_generic_to_shared(dst);
    asm volatile("cp.async.ca.shared.global [%0], [%1], 16, 0;" :: "r"(d), "l"(src));
}
__device__ __forceinline__ void cp_commit() {
    asm volatile("cp.async.commit_group;");
}
__device__ __forceinline__ void cp_wait1() {
    asm volatile("cp.async.wait_group 1;");
}

// Stage one 32-k chunk of the A tile (48 rows x 544 k) directly via cp.async:
// A[rb][k] = { h_row(256) | rolled h_col(256) | x_s(32, masked) } — all k-contiguous.
__device__ __forceinline__ void stage_A(float* As, int c, int m0, int s,
    const float* __restrict__ hrow_in, const float* __restrict__ hcol_in,
    const float* __restrict__ input, int tid)
{
    if (c >= NCHUNK || tid >= 384) return;        // 48 rows x 8 segs of 16B
    int m = tid >> 3, seg = tid & 7;
    int rb = m0 + m;
    float* dst = As + m * KTOT + c * KC + seg * 4;
    if (c < 8) {
        cp16(dst, hrow_in + rb * HID + c * KC + seg * 4);
    } else if (c < 16) {
        int src = rb - B_SZ; if (src < 0) src += RB;
        cp16(dst, hcol_in + src * HID + (c - 8) * KC + seg * 4);
    } else {
        int r = rb >> 5, b = rb & 31, l = s - r;
        if (l >= 0 && l < NROWS)
            cp16(dst, input + (((b * NROWS) + l) * NCOLS + r) * CIN + seg * 4);
        else
            cp16z(dst, input);                     // zero-fill
    }
}

// One recurrence step. Grid (8 j-tiles, 16 m-tiles) = 128 blocks, 512 threads.
// f32x2 packing along K: acc halves hold even/odd-k partial sums.
// Thread tile: 6 rows x 3 gate-cols (gates {gb, gb+2, gb+4}, gb = (tid>>5)&1).
__global__ __launch_bounds__(512, 1)
void step_kernel(const float* __restrict__ input,
                 const float* __restrict__ W,
                 const float* __restrict__ Bp,
                 float* __restrict__ out,
                 int s)
{
    extern __shared__ char smem_raw[];
    float* As = (float*)smem_raw;                                  // [48][544]
    unsigned long long* Wsp = (unsigned long long*)(smem_raw + AS_FLOATS * 4);
    float* Xs = (float*)(Wsp + WS_BUF);   // gate-exchange buffer, aliases W buf 1

    const int tid     = threadIdx.x;
    const int j0      = blockIdx.x * 32;
    const int m0      = blockIdx.y * BM;
    const int slot    = tid & 63;        // gate-col slot (cc = slot + 64q)
    const int rowslot = tid >> 6;        // 0..7, 6 rows each

    const float* __restrict__ hrow_in  = g_hrow[s & 1];
    const float* __restrict__ hcol_in  = g_hcol[s & 1];
    float* __restrict__       hrow_out = g_hrow[(s + 1) & 1];
    float* __restrict__       hcol_out = g_hcol[(s + 1) & 1];

    // W staging plan: 3 float4 per thread per chunk. u = tid + 512t:
    // wrow=u>>3 in [0,192) (= g*32+jl), k4=u&7 -> k-pairs (2k4, 2k4+1).
    const float* wsrc[3];
    int wklp[3], wcc[3];
#pragma unroll
    for (int t = 0; t < 3; ++t) {
        int u = tid + 512 * t;
        int wrow = u >> 3, k4 = u & 7;
        wcc[t]  = wrow;
        wklp[t] = k4 * 2;
        wsrc[t] = W + ((wrow >> 5) * HID + j0 + (wrow & 31)) * KTOT + k4 * 4;
    }

    // prologue: A chunks 0,1 in flight; W chunk 0 in registers
    stage_A(As, 0, m0, s, hrow_in, hcol_in, input, tid); cp_commit();
    stage_A(As, 1, m0, s, hrow_in, hcol_in, input, tid); cp_commit();

    float4 wreg[3];
#pragma unroll
    for (int t = 0; t < 3; ++t) wreg[t] = *(const float4*)(wsrc[t]);

    unsigned long long acc[6][3];
#pragma unroll
    for (int i = 0; i < 6; ++i)
#pragma unroll
        for (int q = 0; q < 3; ++q) acc[i][q] = 0ULL;

    for (int c = 0; c < NCHUNK; ++c) {
        cp_wait1();                                   // A(c) complete

        // STS W(c) into ping-pong buffer
        unsigned long long* wb = Wsp + (c & 1) * WS_BUF;
#pragma unroll
        for (int t = 0; t < 3; ++t) {
            *(float2*)(wb + wklp[t] * WS_STRIDE + wcc[t]) =
                make_float2(wreg[t].x, wreg[t].y);
            *(float2*)(wb + (wklp[t] + 1) * WS_STRIDE + wcc[t]) =
                make_float2(wreg[t].z, wreg[t].w);
        }
        __syncthreads();

        // prefetch next W chunk into registers; next-next A chunk via cp.async
        if (c + 1 < NCHUNK) {
#pragma unroll
            for (int t = 0; t < 3; ++t)
                wreg[t] = *(const float4*)(wsrc[t] + (c + 1) * KC);
        }
        stage_A(As, c + 2, m0, s, hrow_in, hcol_in, input, tid);
        cp_commit();

        // ---- compute chunk c: per 2 k-pairs: 6 LDS.128(A) + 6 LDS.64(W) + 36 FMA2 ----
        const float* ab = As + (rowslot * 6) * KTOT + c * KC;
        const unsigned long long* wbr = wb + slot;
#pragma unroll
        for (int klp2 = 0; klp2 < KP; klp2 += 2) {
            unsigned long long a0[6], a1[6];
#pragma unroll
            for (int i = 0; i < 6; ++i) {
                ulonglong2 av = *(const ulonglong2*)(ab + i * KTOT + klp2 * 2);
                a0[i] = av.x; a1[i] = av.y;
            }
#pragma unroll
            for (int half = 0; half < 2; ++half) {
                unsigned long long w[3];
#pragma unroll
                for (int q = 0; q < 3; ++q)
                    w[q] = wbr[(klp2 + half) * WS_STRIDE + 64 * q];
#pragma unroll
                for (int i = 0; i < 6; ++i) {
                    unsigned long long a = half ? a1[i] : a0[i];
#pragma unroll
                    for (int q = 0; q < 3; ++q)
                        asm("fma.rn.f32x2 %0, %1, %2, %0;"
                            : "+l"(acc[i][q]) : "l"(a), "l"(w[q]));
                }
            }
        }
        // no trailing sync needed: next iter's STS targets the other W buffer,
        // and the next sync (after that STS) orders everything.
    }

    // ---- epilogue: reduce f32x2 halves, exchange gates, PSGMU update ----
    const int jl = slot & 31;
    const int gbase = slot >> 5;           // 0 -> gates {0,2,4}, 1 -> {1,3,5}
    const int j = j0 + jl;

    float bp[3];
#pragma unroll
    for (int q = 0; q < 3; ++q) bp[q] = Bp[(gbase + 2 * q) * HID + j];
    const bool smask = (s < NCOLS);

    float gv[6][3];
#pragma unroll
    for (int i = 0; i < 6; ++i) {
        int rb = m0 + rowslot * 6 + i;
        bool mask = smask && ((rb >> 5) <= s);
#pragma unroll
        for (int q = 0; q < 3; ++q) {
            unsigned long long v = acc[i][q];
            float g = __uint_as_float((unsigned)(v & 0xffffffffULL)) +
                      __uint_as_float((unsigned)(v >> 32));
            gv[i][q] = mask ? (g + bp[q]) : g;
        }
    }

    if (gbase == 1) {   // owns o_row(1), o_col(3), i_col(5): activate + publish
#pragma unroll
        for (int i = 0; i < 6; ++i) {
            int row = rowslot * 6 + i;
            Xs[row * 96 + jl * 3 + 0] = sigmoidf_(gv[i][0]);
            Xs[row * 96 + jl * 3 + 1] = sigmoidf_(gv[i][1]);
            Xs[row * 96 + jl * 3 + 2] = tanhf(gv[i][2]);
        }
    }
    __syncthreads();
    if (gbase == 0) {   // owns u_row(0), u_col(2), i_row(4): finish update
#pragma unroll
        for (int i = 0; i < 6; ++i) {
            int row = rowslot * 6 + i;
            int rb = m0 + row;
            float u_row = sigmoidf_(gv[i][0]);
            float u_col = sigmoidf_(gv[i][1]);
            float i_row = tanhf(gv[i][2]);
            float o_row = Xs[row * 96 + jl * 3 + 0];
            float o_col = Xs[row * 96 + jl * 3 + 1];
            float i_col = Xs[row * 96 + jl * 3 + 2];

            float hro = hrow_in[rb * HID + j];
            int src = rb - B_SZ; if (src < 0) src += RB;
            float hco = hcol_in[src * HID + j];

            float hr = tanhf((1.0f - u_row) * hro + u_row * i_row) * o_row;
            float hc = tanhf((1.0f - u_col) * hco + u_col * i_col) * o_col;

            hrow_out[rb * HID + j] = hr;
            hcol_out[rb * HID + j] = hc;

            float* orow = out + ((size_t)rb * LSTEPS + s) * (2 * HID);
            orow[j]       = hr;
            orow[HID + j] = hc;
        }
    }
}

// Gather hidden_col_all / hidden_row_all from output_all (disjoint regions of d_out).
__global__ void gather_kernel(float* __restrict__ out) {
    int idx = blockIdx.x * blockDim.x + threadIdx.x;
    if (idx < HC_N) {
        int b = idx / (NROWS * HID);
        int t = (idx / HID) % NROWS;
        int j = idx % HID;
        int rb = (NCOLS - 1) * B_SZ + b;
        int ss = (NCOLS - 1) + t;
        out[OUTALL_N + idx] = out[((size_t)rb * LSTEPS + ss) * (2 * HID) + HID + j];
    } else if (idx < HC_N + HR_N) {
        int k = idx - HC_N;
        int b = k / (NCOLS * HID);
        int i = (k / HID) % NCOLS;
        int j = k % HID;
        int rb = i * B_SZ + b;
        int ss = (NROWS - 1) + i;
        out[OUTALL_N + HC_N + k] = out[((size_t)rb * LSTEPS + ss) * (2 * HID) + j];
    }
}

extern "C" void kernel_launch(void* const* d_in, const int* in_sizes, int n_in,
                              void* d_out, int out_size) {
    (void)in_sizes; (void)n_in; (void)out_size;
    const float* input = (const float*)d_in[0];   // (32,48,24,32)
    const float* W     = (const float*)d_in[1];   // (1536,544)
    const float* Bp    = (const float*)d_in[2];   // (1536,)
    float* out = (float*)d_out;

    cudaFuncSetAttribute(step_kernel,
                         cudaFuncAttributeMaxDynamicSharedMemorySize, SMEM_BYTES);

    init_kernel<<<(RB * HID + 255) / 256, 256>>>();

    dim3 grid(HID / 32, RB / BM);   // (8, 16) = 128 blocks
    for (int s = 0; s < LSTEPS; ++s) {
        step_kernel<<<grid, 512, SMEM_BYTES>>>(input, W, Bp, out, s);
    }

    gather_kernel<<<(HC_N + HR_N + 255) / 256, 256>>>(out);
}

// round 7
// speedup vs baseline: 1.5349x; 1.0005x over previous
#include <cuda_runtime.h>

// ---------------- problem constants ----------------
#define B_SZ   32
#define NROWS  48
#define NCOLS  24
#define CIN    32
#define HID    256
#define RB     768      // NCOLS * B_SZ
#define LSTEPS 71
#define KTOT   544      // 2*HID + CIN

// ---------------- tiling ----------------
#define BM     48       // rows per block
#define KC     32       // k per chunk
#define KP     16       // k-pairs per chunk
#define NCHUNK 17       // 544/32
#define WS_STRIDE 193   // 8-byte elements per klp row (192 cols + 1 pad)
#define WS_BUF (KP*WS_STRIDE)          // ull per W buffer
#define AS_FLOATS (BM*KTOT)            // 26112 floats
#define SMEM_BYTES (AS_FLOATS*4 + 2*WS_BUF*8)   // 104448 + 49408 = 153856

// out layout: [output_all (768,71,512)] [hidden_col (32,48,256)] [hidden_row (32,24,256)]
#define OUTALL_N  (RB * LSTEPS * 2 * HID)
#define HC_N      (B_SZ * NROWS * HID)
#define HR_N      (B_SZ * NCOLS * HID)

__device__ float g_hrow[2][RB * HID];
__device__ float g_hcol[2][RB * HID];

__global__ void init_kernel() {
    int idx = blockIdx.x * blockDim.x + threadIdx.x;
    if (idx < RB * HID) {
        g_hrow[0][idx] = 0.0f;
        g_hcol[0][idx] = 0.0f;
    }
}

__device__ __forceinline__ float sigmoidf_(float x) {
    return 1.0f / (1.0f + expf(-x));
}

__device__ __forceinline__ void cp16(void* dst, const void* src) {
    unsigned d = (unsigned)__cvta_generic_to_shared(dst);
    asm volatile("cp.async.ca.shared.global [%0], [%1], 16;" :: "r"(d), "l"(src));
}
__device__ __forceinline__ void cp16z(void* dst, const void* src) {
    unsigned d = (unsigned)__cvta_generic_to_shared(dst);
    asm volatile("cp.async.ca.shared.global [%0], [%1], 16, 0;" :: "r"(d), "l"(src));
}
__device__ __forceinline__ void cp_commit() {
    asm volatile("cp.async.commit_group;");
}
__device__ __forceinline__ void cp_wait1() {
    asm volatile("cp.async.wait_group 1;");
}

// Stage one 32-k chunk of the A tile (48 rows x 544 k) directly via cp.async:
// A[rb][k] = { h_row(256) | rolled h_col(256) | x_s(32, masked) } — all k-contiguous.
__device__ __forceinline__ void stage_A(float* As, int c, int m0, int s,
    const float* __restrict__ hrow_in, const float* __restrict__ hcol_in,
    const float* __restrict__ input, int tid)
{
    if (c >= NCHUNK || tid >= 384) return;        // 48 rows x 8 segs of 16B
    int m = tid >> 3, seg = tid & 7;
    int rb = m0 + m;
    float* dst = As + m * KTOT + c * KC + seg * 4;
    if (c < 8) {
        cp16(dst, hrow_in + rb * HID + c * KC + seg * 4);
    } else if (c < 16) {
        int src = rb - B_SZ; if (src < 0) src += RB;
        cp16(dst, hcol_in + src * HID + (c - 8) * KC + seg * 4);
    } else {
        int r = rb >> 5, b = rb & 31, l = s - r;
        if (l >= 0 && l < NROWS)
            cp16(dst, input + (((b * NROWS) + l) * NCOLS + r) * CIN + seg * 4);
        else
            cp16z(dst, input);                     // zero-fill
    }
}

// One recurrence step. Grid (8 j-tiles, 16 m-tiles) = 128 blocks, 512 threads.
// f32x2 packing along K: acc halves hold even/odd-k partial sums.
// Thread tile: 6 rows x 3 gate-cols (gates {gb, gb+2, gb+4}, gb = (tid>>5)&1).
__global__ __launch_bounds__(512, 1)
void step_kernel(const float* __restrict__ input,
                 const float* __restrict__ W,
                 const float* __restrict__ Bp,
                 float* __restrict__ out,
                 int s)
{
    extern __shared__ char smem_raw[];
    float* As = (float*)smem_raw;                                  // [48][544]
    unsigned long long* Wsp = (unsigned long long*)(smem_raw + AS_FLOATS * 4);
    float* Xs = (float*)(Wsp + WS_BUF);   // gate-exchange buffer, aliases W buf 1

    const int tid     = threadIdx.x;
    const int j0      = blockIdx.x * 32;
    const int m0      = blockIdx.y * BM;
    const int slot    = tid & 63;        // gate-col slot (cc = slot + 64q)
    const int rowslot = tid >> 6;        // 0..7, 6 rows each

    const float* __restrict__ hrow_in  = g_hrow[s & 1];
    const float* __restrict__ hcol_in  = g_hcol[s & 1];
    float* __restrict__       hrow_out = g_hrow[(s + 1) & 1];
    float* __restrict__       hcol_out = g_hcol[(s + 1) & 1];

    // W staging plan: 3 float4 per thread per chunk. u = tid + 512t:
    // wrow=u>>3 in [0,192) (= g*32+jl), k4=u&7 -> k-pairs (2k4, 2k4+1).
    const float* wsrc[3];
    int wklp[3], wcc[3];
#pragma unroll
    for (int t = 0; t < 3; ++t) {
        int u = tid + 512 * t;
        int wrow = u >> 3, k4 = u & 7;
        wcc[t]  = wrow;
        wklp[t] = k4 * 2;
        wsrc[t] = W + ((wrow >> 5) * HID + j0 + (wrow & 31)) * KTOT + k4 * 4;
    }

    // prologue: A chunks 0,1 in flight; W chunk 0 in registers
    stage_A(As, 0, m0, s, hrow_in, hcol_in, input, tid); cp_commit();
    stage_A(As, 1, m0, s, hrow_in, hcol_in, input, tid); cp_commit();

    float4 wreg[3];
#pragma unroll
    for (int t = 0; t < 3; ++t) wreg[t] = *(const float4*)(wsrc[t]);

    unsigned long long acc[6][3];
#pragma unroll
    for (int i = 0; i < 6; ++i)
#pragma unroll
        for (int q = 0; q < 3; ++q) acc[i][q] = 0ULL;

    for (int c = 0; c < NCHUNK; ++c) {
        cp_wait1();                                   // A(c) complete

        // STS W(c) into ping-pong buffer
        unsigned long long* wb = Wsp + (c & 1) * WS_BUF;
#pragma unroll
        for (int t = 0; t < 3; ++t) {
            *(float2*)(wb + wklp[t] * WS_STRIDE + wcc[t]) =
                make_float2(wreg[t].x, wreg[t].y);
            *(float2*)(wb + (wklp[t] + 1) * WS_STRIDE + wcc[t]) =
                make_float2(wreg[t].z, wreg[t].w);
        }
        __syncthreads();

        // prefetch next W chunk into registers; next-next A chunk via cp.async
        if (c + 1 < NCHUNK) {
#pragma unroll
            for (int t = 0; t < 3; ++t)
                wreg[t] = *(const float4*)(wsrc[t] + (c + 1) * KC);
        }
        stage_A(As, c + 2, m0, s, hrow_in, hcol_in, input, tid);
        cp_commit();

        // ---- compute chunk c: per 2 k-pairs: 6 LDS.128(A) + 6 LDS.64(W) + 36 FMA2 ----
        const float* ab = As + (rowslot * 6) * KTOT + c * KC;
        const unsigned long long* wbr = wb + slot;
#pragma unroll
        for (int klp2 = 0; klp2 < KP; klp2 += 2) {
            unsigned long long a0[6], a1[6];
#pragma unroll
            for (int i = 0; i < 6; ++i) {
                ulonglong2 av = *(const ulonglong2*)(ab + i * KTOT + klp2 * 2);
                a0[i] = av.x; a1[i] = av.y;
            }
#pragma unroll
            for (int half = 0; half < 2; ++half) {
                unsigned long long w[3];
#pragma unroll
                for (int q = 0; q < 3; ++q)
                    w[q] = wbr[(klp2 + half) * WS_STRIDE + 64 * q];
#pragma unroll
                for (int i = 0; i < 6; ++i) {
                    unsigned long long a = half ? a1[i] : a0[i];
#pragma unroll
                    for (int q = 0; q < 3; ++q)
                        asm("fma.rn.f32x2 %0, %1, %2, %0;"
                            : "+l"(acc[i][q]) : "l"(a), "l"(w[q]));
                }
            }
        }
        // no trailing sync needed: next iter's STS targets the other W buffer,
        // and the next sync (after that STS) orders everything.
    }

    // ---- epilogue: reduce f32x2 halves, exchange gates, PSGMU update ----
    const int jl = slot & 31;
    const int gbase = slot >> 5;           // 0 -> gates {0,2,4}, 1 -> {1,3,5}
    const int j = j0 + jl;

    float bp[3];
#pragma unroll
    for (int q = 0; q < 3; ++q) bp[q] = Bp[(gbase + 2 * q) * HID + j];
    const bool smask = (s < NCOLS);

    float gv[6][3];
#pragma unroll
    for (int i = 0; i < 6; ++i) {
        int rb = m0 + rowslot * 6 + i;
        bool mask = smask && ((rb >> 5) <= s);
#pragma unroll
        for (int q = 0; q < 3; ++q) {
            unsigned long long v = acc[i][q];
            float g = __uint_as_float((unsigned)(v & 0xffffffffULL)) +
                      __uint_as_float((unsigned)(v >> 32));
            gv[i][q] = mask ? (g + bp[q]) : g;
        }
    }

    if (gbase == 1) {   // owns o_row(1), o_col(3), i_col(5): activate + publish
#pragma unroll
        for (int i = 0; i < 6; ++i) {
            int row = rowslot * 6 + i;
            Xs[row * 96 + jl * 3 + 0] = sigmoidf_(gv[i][0]);
            Xs[row * 96 + jl * 3 + 1] = sigmoidf_(gv[i][1]);
            Xs[row * 96 + jl * 3 + 2] = tanhf(gv[i][2]);
        }
    }
    __syncthreads();
    if (gbase == 0) {   // owns u_row(0), u_col(2), i_row(4): finish update
#pragma unroll
        for (int i = 0; i < 6; ++i) {
            int row = rowslot * 6 + i;
            int rb = m0 + row;
            float u_row = sigmoidf_(gv[i][0]);
            float u_col = sigmoidf_(gv[i][1]);
            float i_row = tanhf(gv[i][2]);
            float o_row = Xs[row * 96 + jl * 3 + 0];
            float o_col = Xs[row * 96 + jl * 3 + 1];
            float i_col = Xs[row * 96 + jl * 3 + 2];

            float hro = hrow_in[rb * HID + j];
            int src = rb - B_SZ; if (src < 0) src += RB;
            float hco = hcol_in[src * HID + j];

            float hr = tanhf((1.0f - u_row) * hro + u_row * i_row) * o_row;
            float hc = tanhf((1.0f - u_col) * hco + u_col * i_col) * o_col;

            hrow_out[rb * HID + j] = hr;
            hcol_out[rb * HID + j] = hc;

            float* orow = out + ((size_t)rb * LSTEPS + s) * (2 * HID);
            orow[j]       = hr;
            orow[HID + j] = hc;
        }
    }
}

// Gather hidden_col_all / hidden_row_all from output_all (disjoint regions of d_out).
__global__ void gather_kernel(float* __restrict__ out) {
    int idx = blockIdx.x * blockDim.x + threadIdx.x;
    if (idx < HC_N) {
        int b = idx / (NROWS * HID);
        int t = (idx / HID) % NROWS;
        int j = idx % HID;
        int rb = (NCOLS - 1) * B_SZ + b;
        int ss = (NCOLS - 1) + t;
        out[OUTALL_N + idx] = out[((size_t)rb * LSTEPS + ss) * (2 * HID) + HID + j];
    } else if (idx < HC_N + HR_N) {
        int k = idx - HC_N;
        int b = k / (NCOLS * HID);
        int i = (k / HID) % NCOLS;
        int j = k % HID;
        int rb = i * B_SZ + b;
        int ss = (NROWS - 1) + i;
        out[OUTALL_N + HC_N + k] = out[((size_t)rb * LSTEPS + ss) * (2 * HID) + j];
    }
}

extern "C" void kernel_launch(void* const* d_in, const int* in_sizes, int n_in,
                              void* d_out, int out_size) {
    (void)in_sizes; (void)n_in; (void)out_size;
    const float* input = (const float*)d_in[0];   // (32,48,24,32)
    const float* W     = (const float*)d_in[1];   // (1536,544)
    const float* Bp    = (const float*)d_in[2];   // (1536,)
    float* out = (float*)d_out;

    cudaFuncSetAttribute(step_kernel,
                         cudaFuncAttributeMaxDynamicSharedMemorySize, SMEM_BYTES);

    init_kernel<<<(RB * HID + 255) / 256, 256>>>();

    dim3 grid(HID / 32, RB / BM);   // (8, 16) = 128 blocks
    for (int s = 0; s < LSTEPS; ++s) {
        step_kernel<<<grid, 512, SMEM_BYTES>>>(input, W, Bp, out, s);
    }

    gather_kernel<<<(HC_N + HR_N + 255) / 256, 256>>>(out);
}